// round 14
// baseline (speedup 1.0000x reference)
#include <cuda_runtime.h>
#include <cuda_bf16.h>
#include <math.h>
#include <cstdint>

#define NSEQ 1024
#define DM 512
#define NH 8
#define DK 64

// scratch (no cudaMalloc allowed)
__device__ float g_q[NSEQ * DM];
__device__ float g_k[NSEQ * DM];
__device__ float g_v[NSEQ * DM];
__device__ float g_attn[NSEQ * DM];
__device__ float g_pv[NSEQ * DM];
__device__ float g_qk[(size_t)NH * NSEQ * NSEQ];          // 32MB: scores -> probs (in place)
__device__ __nv_bfloat16 g_sv[(size_t)NSEQ * NSEQ * DK];  // 128MB: structure-value proj

__device__ __forceinline__ unsigned f2tf(float f) {
    unsigned u; asm("cvt.rna.tf32.f32 %0, %1;" : "=r"(u) : "f"(f)); return u;
}
__device__ __forceinline__ void mma8(float* c, unsigned a0, unsigned a1, unsigned a2,
                                     unsigned a3, unsigned b0, unsigned b1) {
    asm("mma.sync.aligned.m16n8k8.row.col.f32.tf32.tf32.f32 "
        "{%0,%1,%2,%3},{%4,%5,%6,%7},{%8,%9},{%0,%1,%2,%3};"
        : "+f"(c[0]), "+f"(c[1]), "+f"(c[2]), "+f"(c[3])
        : "r"(a0), "r"(a1), "r"(a2), "r"(a3), "r"(b0), "r"(b1));
}

// ---------------------------------------------------------------------------
// Projection GEMM via 3xTF32 (hh + hl + lh => fp32-grade accuracy).
// Shared device body; qkv_proj packs Q/K/V into one launch via blockIdx.z.
// ---------------------------------------------------------------------------
__device__ __forceinline__ void proj_body(
    const float* __restrict__ A, const float* __restrict__ W,
    const float* __restrict__ bias, float* __restrict__ C, int relu,
    int bm, int bn)
{
    __shared__ unsigned sAhi[64 * 36], sAlo[64 * 36];
    __shared__ unsigned sWhi[32 * 68], sWlo[32 * 68];
    const int t = threadIdx.x, lane = t & 31, w = t >> 5;
    const int g = lane >> 2, tig = lane & 3;
    const int wm = w & 3, wn = w >> 2;

    float c[4][4] = {};

    for (int k0 = 0; k0 < DM; k0 += 32) {
        __syncthreads();
        #pragma unroll
        for (int u = 0; u < 2; u++) {
            int f4 = t + 256 * u;
            {
                int r = f4 >> 3, c4 = (f4 & 7) * 4;
                float4 v = *(const float4*)&A[(size_t)(bm + r) * DM + k0 + c4];
                unsigned* dh = sAhi + r * 36 + c4;
                unsigned* dl = sAlo + r * 36 + c4;
                unsigned h0 = f2tf(v.x), h1 = f2tf(v.y), h2 = f2tf(v.z), h3 = f2tf(v.w);
                dh[0] = h0; dh[1] = h1; dh[2] = h2; dh[3] = h3;
                dl[0] = f2tf(v.x - __uint_as_float(h0));
                dl[1] = f2tf(v.y - __uint_as_float(h1));
                dl[2] = f2tf(v.z - __uint_as_float(h2));
                dl[3] = f2tf(v.w - __uint_as_float(h3));
            }
            {
                int r = f4 >> 4, c4 = (f4 & 15) * 4;
                float4 v = *(const float4*)&W[(size_t)(k0 + r) * DM + bn + c4];
                unsigned* dh = sWhi + r * 68 + c4;
                unsigned* dl = sWlo + r * 68 + c4;
                unsigned h0 = f2tf(v.x), h1 = f2tf(v.y), h2 = f2tf(v.z), h3 = f2tf(v.w);
                dh[0] = h0; dh[1] = h1; dh[2] = h2; dh[3] = h3;
                dl[0] = f2tf(v.x - __uint_as_float(h0));
                dl[1] = f2tf(v.y - __uint_as_float(h1));
                dl[2] = f2tf(v.z - __uint_as_float(h2));
                dl[3] = f2tf(v.w - __uint_as_float(h3));
            }
        }
        __syncthreads();
        #pragma unroll
        for (int ks = 0; ks < 4; ks++) {
            int k8 = ks * 8;
            int r0 = wm * 16;
            unsigned ah0 = sAhi[(r0 + g) * 36 + k8 + tig];
            unsigned ah1 = sAhi[(r0 + g + 8) * 36 + k8 + tig];
            unsigned ah2 = sAhi[(r0 + g) * 36 + k8 + tig + 4];
            unsigned ah3 = sAhi[(r0 + g + 8) * 36 + k8 + tig + 4];
            unsigned al0 = sAlo[(r0 + g) * 36 + k8 + tig];
            unsigned al1 = sAlo[(r0 + g + 8) * 36 + k8 + tig];
            unsigned al2 = sAlo[(r0 + g) * 36 + k8 + tig + 4];
            unsigned al3 = sAlo[(r0 + g + 8) * 36 + k8 + tig + 4];
            #pragma unroll
            for (int nt = 0; nt < 4; nt++) {
                int n = wn * 32 + nt * 8;
                unsigned bh0 = sWhi[(k8 + tig) * 68 + n + g];
                unsigned bh1 = sWhi[(k8 + tig + 4) * 68 + n + g];
                unsigned bl0 = sWlo[(k8 + tig) * 68 + n + g];
                unsigned bl1 = sWlo[(k8 + tig + 4) * 68 + n + g];
                mma8(c[nt], ah0, ah1, ah2, ah3, bh0, bh1);
                mma8(c[nt], ah0, ah1, ah2, ah3, bl0, bl1);
                mma8(c[nt], al0, al1, al2, al3, bh0, bh1);
            }
        }
    }
    #pragma unroll
    for (int nt = 0; nt < 4; nt++) {
        int cc = bn + wn * 32 + nt * 8 + 2 * tig;
        int r  = bm + wm * 16 + g;
        float b0v = bias[cc], b1v = bias[cc + 1];
        float v00 = c[nt][0] + b0v, v01 = c[nt][1] + b1v;
        float v10 = c[nt][2] + b0v, v11 = c[nt][3] + b1v;
        if (relu) {
            v00 = fmaxf(v00, 0.f); v01 = fmaxf(v01, 0.f);
            v10 = fmaxf(v10, 0.f); v11 = fmaxf(v11, 0.f);
        }
        *(float2*)&C[(size_t)r * DM + cc]       = make_float2(v00, v01);
        *(float2*)&C[(size_t)(r + 8) * DM + cc] = make_float2(v10, v11);
    }
}

__global__ void __launch_bounds__(256) proj_mma(
    const float* __restrict__ A, const float* __restrict__ W,
    const float* __restrict__ bias, float* __restrict__ C, int relu)
{
    proj_body(A, W, bias, C, relu, blockIdx.y * 64, blockIdx.x * 64);
}

// One launch for Q, K, V: blockIdx.z selects weights/bias/output/relu.
__global__ void __launch_bounds__(256) qkv_proj(
    const float* __restrict__ x,
    const float* __restrict__ Wq, const float* __restrict__ bq,
    const float* __restrict__ Wk, const float* __restrict__ bk,
    const float* __restrict__ Wv, const float* __restrict__ bv)
{
    const float* W;
    const float* b;
    float* C;
    int relu;
    if (blockIdx.z == 0)      { W = Wq; b = bq; C = g_q; relu = 1; }
    else if (blockIdx.z == 1) { W = Wk; b = bk; C = g_k; relu = 1; }
    else                      { W = Wv; b = bv; C = g_v; relu = 0; }
    proj_body(x, W, b, C, relu, blockIdx.y * 64, blockIdx.x * 64);
}

// ---------------------------------------------------------------------------
// QK precompute: g_qk[h,i,j] = sum_d q[i,h,d]*k[j,h,d]  (raw, unscaled)
// ---------------------------------------------------------------------------
#define QK_SMEM (2 * 128 * 68 * 4)
__global__ void __launch_bounds__(256) qk_mma()
{
    extern __shared__ unsigned sm[];
    unsigned* sQ = sm;
    unsigned* sK = sm + 128 * 68;
    const int t = threadIdx.x, lane = t & 31, w = t >> 5;
    const int g = lane >> 2, tig = lane & 3;
    const int h = blockIdx.z, i0 = blockIdx.y * 128, j0 = blockIdx.x * 128;

    #pragma unroll
    for (int u = 0; u < 8; u++) {
        int f4 = t + 256 * u;
        int row = f4 >> 4;
        int c4 = (f4 & 15) * 4;
        float4 qv = *(const float4*)&g_q[(size_t)(i0 + row) * DM + h * DK + c4];
        unsigned* dq = sQ + row * 68 + c4;
        dq[0] = f2tf(qv.x); dq[1] = f2tf(qv.y); dq[2] = f2tf(qv.z); dq[3] = f2tf(qv.w);
        float4 kv = *(const float4*)&g_k[(size_t)(j0 + row) * DM + h * DK + c4];
        unsigned* dk = sK + row * 68 + c4;
        dk[0] = f2tf(kv.x); dk[1] = f2tf(kv.y); dk[2] = f2tf(kv.z); dk[3] = f2tf(kv.w);
    }
    __syncthreads();

    float c[16][4] = {};
    #pragma unroll
    for (int k0 = 0; k0 < 64; k0 += 8) {
        unsigned a0 = sQ[(16 * w + g) * 68 + k0 + tig];
        unsigned a1 = sQ[(16 * w + g + 8) * 68 + k0 + tig];
        unsigned a2 = sQ[(16 * w + g) * 68 + k0 + tig + 4];
        unsigned a3 = sQ[(16 * w + g + 8) * 68 + k0 + tig + 4];
        #pragma unroll
        for (int nt = 0; nt < 16; nt++) {
            unsigned b0 = sK[(8 * nt + g) * 68 + k0 + tig];
            unsigned b1 = sK[(8 * nt + g) * 68 + k0 + tig + 4];
            mma8(c[nt], a0, a1, a2, a3, b0, b1);
        }
    }
    size_t base = ((size_t)h << 20);
    #pragma unroll
    for (int nt = 0; nt < 16; nt++) {
        int jj = j0 + 8 * nt + 2 * tig;
        int ii = i0 + 16 * w + g;
        *(float2*)&g_qk[base + (size_t)ii * NSEQ + jj] = make_float2(c[nt][0], c[nt][1]);
        *(float2*)&g_qk[base + (size_t)(ii + 8) * NSEQ + jj] = make_float2(c[nt][2], c[nt][3]);
    }
}

// ---------------------------------------------------------------------------
// edge_fused: grid (2 j-halves, 1024 i); each CTA does 4 j-tiles of 128.
// Per tile: [128j x 64e] @ [64e x 128dd] tf32 MMA.
//   ng==0 warps (cols 0..63): sk = relu(.+bsk) -> sSK (tf32, smem)
//   ng==1 warps (cols 64..127): sv = .+bsv -> bf16 -> g_sv DIRECT from regs
//   score MMA: sk @ qT -> g_qk[h,i,j] = (qk + q.sk)*0.125  (in place)
// 2 syncthreads per tile (sE(t+1) fenced by sync_B(t); sSK(t+1) by sync_A(t+1)).
// smem words: sW 8704 | sE 8704 | sSK 8704 | sQT 576 | sB 128
// ---------------------------------------------------------------------------
#define P2_SMEM ((8704 * 3 + 576 + 128) * 4)
__global__ void __launch_bounds__(256, 2) edge_fused(
    const float* __restrict__ S,
    const float* __restrict__ Wsk, const float* __restrict__ bsk,
    const float* __restrict__ Wsv, const float* __restrict__ bsv)
{
    extern __shared__ unsigned sm2[];
    unsigned* sW  = sm2;                 // [64][136]
    unsigned* sE  = sm2 + 8704;          // [128][68] tf32 E
    unsigned* sSK = sm2 + 17408;         // [128][68] tf32 sk
    unsigned* sQT = sm2 + 26112;         // [64][9]
    float*    sB  = (float*)(sm2 + 26688); // bsk[0:64) | bsv[64:128)

    const int t = threadIdx.x, lane = t & 31, w = t >> 5;
    const int g = lane >> 2, tig = lane & 3;
    const int i  = blockIdx.y;
    const int jh = blockIdx.x;           // j half: 0 or 1
    const int mq = w & 3, ng = w >> 2;

    const float4* Srow = (const float4*)(S + ((size_t)i * NSEQ + jh * 512) * 64);

    // deep prefetch of tile 0
    float4 pre[8];
    #pragma unroll
    for (int u = 0; u < 8; u++) pre[u] = Srow[t + 256 * u];

    // stage W (Wsk|Wsv) as tf32, pitch 136 (once)
    #pragma unroll
    for (int u = 0; u < 8; u++) {
        int f4 = t + 256 * u;
        int e = f4 >> 5;
        int c4 = (f4 & 31) * 4;
        const float* src = (c4 < 64) ? (Wsk + e * 64 + c4) : (Wsv + e * 64 + c4 - 64);
        float4 v = *(const float4*)src;
        unsigned* dst = sW + e * 136 + c4;
        dst[0] = f2tf(v.x); dst[1] = f2tf(v.y); dst[2] = f2tf(v.z); dst[3] = f2tf(v.w);
    }
    // stage qT [d][h] (once)
    #pragma unroll
    for (int u = 0; u < 2; u++) {
        int idx = t + 256 * u;
        sQT[(idx & 63) * 9 + (idx >> 6)] = f2tf(g_q[(size_t)i * DM + idx]);
    }
    if (t < 128) sB[t] = (t < 64) ? bsk[t] : bsv[t - 64];

    for (int jt = 0; jt < 4; jt++) {
        const int j0 = jh * 512 + jt * 128;
        // STS E tile from prefetch regs (tf32)
        #pragma unroll
        for (int u = 0; u < 8; u++) {
            int f4 = t + 256 * u;
            int j = f4 >> 4;
            int e4 = (f4 & 15) * 4;
            unsigned* dst = sE + j * 68 + e4;
            dst[0] = f2tf(pre[u].x); dst[1] = f2tf(pre[u].y);
            dst[2] = f2tf(pre[u].z); dst[3] = f2tf(pre[u].w);
        }
        __syncthreads();   // sync_A: sE ready (and prev tile's score reads done)

        // GEMM1: warp = (mq -> 32 rows, ng -> 64 cols)
        float c[2][8][4] = {};
        #pragma unroll
        for (int k = 0; k < 8; k++) {
            int k0 = k * 8;
            unsigned a[2][4];
            #pragma unroll
            for (int mt = 0; mt < 2; mt++) {
                int r0 = mq * 32 + mt * 16;
                a[mt][0] = sE[(r0 + g) * 68 + k0 + tig];
                a[mt][1] = sE[(r0 + g + 8) * 68 + k0 + tig];
                a[mt][2] = sE[(r0 + g) * 68 + k0 + tig + 4];
                a[mt][3] = sE[(r0 + g + 8) * 68 + k0 + tig + 4];
            }
            #pragma unroll
            for (int nt = 0; nt < 8; nt++) {
                int dd = ng * 64 + nt * 8;
                unsigned b0 = sW[(k0 + tig) * 136 + dd + g];
                unsigned b1 = sW[(k0 + tig + 4) * 136 + dd + g];
                mma8(c[0][nt], a[0][0], a[0][1], a[0][2], a[0][3], b0, b1);
                mma8(c[1][nt], a[1][0], a[1][1], a[1][2], a[1][3], b0, b1);
            }
        }

        if (ng == 0) {
            // sk = relu(c + bsk) -> sSK (tf32)
            #pragma unroll
            for (int mt = 0; mt < 2; mt++) {
                int r0 = mq * 32 + mt * 16;
                #pragma unroll
                for (int nt = 0; nt < 8; nt++) {
                    int dd = nt * 8 + 2 * tig;
                    float b0v = sB[dd], b1v = sB[dd + 1];
                    sSK[(r0 + g) * 68 + dd]         = f2tf(fmaxf(c[mt][nt][0] + b0v, 0.f));
                    sSK[(r0 + g) * 68 + dd + 1]     = f2tf(fmaxf(c[mt][nt][1] + b1v, 0.f));
                    sSK[(r0 + g + 8) * 68 + dd]     = f2tf(fmaxf(c[mt][nt][2] + b0v, 0.f));
                    sSK[(r0 + g + 8) * 68 + dd + 1] = f2tf(fmaxf(c[mt][nt][3] + b1v, 0.f));
                }
            }
        } else {
            // sv = c + bsv -> bf16 -> g_sv, straight from registers.
            // Row j's full 128B is written by this warp (nt covers all 64 cols),
            // so L2 line-coalescing repairs the 16B/sector pattern.
            char* base = (char*)g_sv + (((size_t)i << 10) + j0) * 128;
            #pragma unroll
            for (int mt = 0; mt < 2; mt++) {
                int r0 = mq * 32 + mt * 16 + g;
                #pragma unroll
                for (int nt = 0; nt < 8; nt++) {
                    int dv = nt * 8 + 2 * tig;
                    float b0v = sB[64 + dv], b1v = sB[64 + dv + 1];
                    __nv_bfloat162 p0 = __float22bfloat162_rn(
                        make_float2(c[mt][nt][0] + b0v, c[mt][nt][1] + b1v));
                    __nv_bfloat162 p1 = __float22bfloat162_rn(
                        make_float2(c[mt][nt][2] + b0v, c[mt][nt][3] + b1v));
                    *(__nv_bfloat162*)(base + (size_t)r0 * 128 + dv * 2)       = p0;
                    *(__nv_bfloat162*)(base + (size_t)(r0 + 8) * 128 + dv * 2) = p1;
                }
            }
        }

        // prefetch next tile (overlaps epilogue + score)
        if (jt < 3) {
            #pragma unroll
            for (int u = 0; u < 8; u++) pre[u] = Srow[(jt + 1) * 2048 + t + 256 * u];
        }
        __syncthreads();   // sync_B: sSK complete; all GEMM reads of sE done

        // score MMA: s2[128j x 8h] = sk @ qT ; warp w = m16 tile
        float cs[4] = {};
        #pragma unroll
        for (int k = 0; k < 8; k++) {
            int k0 = k * 8;
            unsigned a0 = sSK[(16 * w + g) * 68 + k0 + tig];
            unsigned a1 = sSK[(16 * w + g + 8) * 68 + k0 + tig];
            unsigned a2 = sSK[(16 * w + g) * 68 + k0 + tig + 4];
            unsigned a3 = sSK[(16 * w + g + 8) * 68 + k0 + tig + 4];
            unsigned b0 = sQT[(k0 + tig) * 9 + g];
            unsigned b1 = sQT[(k0 + tig + 4) * 9 + g];
            mma8(cs, a0, a1, a2, a3, b0, b1);
        }
        {
            int h0 = 2 * tig;
            int jr = 16 * w + g;
            size_t ibase = ((size_t)i << 10) + j0;
            size_t p00 = ((size_t)h0 << 20) + ibase + jr;
            size_t p01 = ((size_t)(h0 + 1) << 20) + ibase + jr;
            g_qk[p00]     = (g_qk[p00]     + cs[0]) * 0.125f;
            g_qk[p01]     = (g_qk[p01]     + cs[1]) * 0.125f;
            g_qk[p00 + 8] = (g_qk[p00 + 8] + cs[2]) * 0.125f;
            g_qk[p01 + 8] = (g_qk[p01 + 8] + cs[3]) * 0.125f;
        }
        // no third sync: next STS-E only touches sE (fenced by sync_B above);
        // next sSK write happens after next sync_A.
    }
}

// ---------------------------------------------------------------------------
// softmax over rows of g_qk (8192 rows of 1024), normalized, in place.
// ---------------------------------------------------------------------------
__global__ void __launch_bounds__(256) softmax_rows()
{
    __shared__ float rbuf[8];
    const int t = threadIdx.x, lane = t & 31, w = t >> 5;
    float4* row4 = (float4*)(g_qk + ((size_t)blockIdx.x << 10));
    float4 v = row4[t];

    float mx = fmaxf(fmaxf(v.x, v.y), fmaxf(v.z, v.w));
    #pragma unroll
    for (int o = 16; o > 0; o >>= 1) mx = fmaxf(mx, __shfl_xor_sync(0xffffffffu, mx, o));
    if (lane == 0) rbuf[w] = mx;
    __syncthreads();
    if (t < 32) {
        float z = (lane < 8) ? rbuf[lane] : -1e30f;
        #pragma unroll
        for (int o = 4; o > 0; o >>= 1) z = fmaxf(z, __shfl_xor_sync(0xffffffffu, z, o));
        if (lane == 0) rbuf[0] = z;
    }
    __syncthreads();
    float m = rbuf[0];
    __syncthreads();

    float4 e;
    e.x = __expf(v.x - m); e.y = __expf(v.y - m);
    e.z = __expf(v.z - m); e.w = __expf(v.w - m);
    float s = e.x + e.y + e.z + e.w;
    #pragma unroll
    for (int o = 16; o > 0; o >>= 1) s += __shfl_xor_sync(0xffffffffu, s, o);
    if (lane == 0) rbuf[w] = s;
    __syncthreads();
    if (t < 32) {
        float z = (lane < 8) ? rbuf[lane] : 0.f;
        #pragma unroll
        for (int o = 4; o > 0; o >>= 1) z += __shfl_xor_sync(0xffffffffu, z, o);
        if (lane == 0) rbuf[0] = z;
    }
    __syncthreads();
    float inv = 1.0f / rbuf[0];
    e.x *= inv; e.y *= inv; e.z *= inv; e.w *= inv;
    row4[t] = e;
}

// ---------------------------------------------------------------------------
// pv_gemm: PV[i, h*64+d] = sum_j p[h,i,j] * v[j, h*64+d]. grid (16 it, 8 h).
// ---------------------------------------------------------------------------
__global__ void __launch_bounds__(256) pv_gemm()
{
    __shared__ unsigned sP[64 * 68];
    __shared__ unsigned sV[64 * 68];
    const int t = threadIdx.x, lane = t & 31, w = t >> 5;
    const int g = lane >> 2, tig = lane & 3;
    const int i0 = blockIdx.x * 64, h = blockIdx.y;
    const int m = w & 3, nh = w >> 2;

    float c[4][4] = {};
    for (int j0 = 0; j0 < NSEQ; j0 += 64) {
        __syncthreads();
        #pragma unroll
        for (int u = 0; u < 4; u++) {
            int f4 = t + 256 * u;
            int r = f4 >> 4;
            int c4 = (f4 & 15) * 4;
            float4 pv = *(const float4*)&g_qk[((size_t)h << 20) + ((size_t)(i0 + r) << 10) + j0 + c4];
            unsigned* dp = sP + r * 68 + c4;
            dp[0] = f2tf(pv.x); dp[1] = f2tf(pv.y); dp[2] = f2tf(pv.z); dp[3] = f2tf(pv.w);
            float4 vv = *(const float4*)&g_v[(size_t)(j0 + r) * DM + h * DK + c4];
            unsigned* dv = sV + r * 68 + c4;
            dv[0] = f2tf(vv.x); dv[1] = f2tf(vv.y); dv[2] = f2tf(vv.z); dv[3] = f2tf(vv.w);
        }
        __syncthreads();
        #pragma unroll
        for (int k = 0; k < 8; k++) {
            int k0 = k * 8;
            unsigned a0 = sP[(m * 16 + g) * 68 + k0 + tig];
            unsigned a1 = sP[(m * 16 + g + 8) * 68 + k0 + tig];
            unsigned a2 = sP[(m * 16 + g) * 68 + k0 + tig + 4];
            unsigned a3 = sP[(m * 16 + g + 8) * 68 + k0 + tig + 4];
            #pragma unroll
            for (int nt = 0; nt < 4; nt++) {
                int d = nh * 32 + nt * 8;
                unsigned b0 = sV[(k0 + tig) * 68 + d + g];
                unsigned b1 = sV[(k0 + tig + 4) * 68 + d + g];
                mma8(c[nt], a0, a1, a2, a3, b0, b1);
            }
        }
    }
    #pragma unroll
    for (int nt = 0; nt < 4; nt++) {
        int d = h * 64 + nh * 32 + nt * 8 + 2 * tig;
        int r = i0 + m * 16 + g;
        *(float2*)&g_pv[(size_t)r * DM + d]       = make_float2(c[nt][0], c[nt][1]);
        *(float2*)&g_pv[(size_t)(r + 8) * DM + d] = make_float2(c[nt][2], c[nt][3]);
    }
}

// ---------------------------------------------------------------------------
// sv_agg (tf32 MMA): attn[i,h*64+d] = PV + sum_j p[h,i,j]*sv[i,j,d].
// ---------------------------------------------------------------------------
__global__ void __launch_bounds__(256) sv_agg()
{
    __shared__ unsigned sSv[128 * 68];
    __shared__ unsigned pHT[8 * 132];
    const int t = threadIdx.x, lane = t & 31, w = t >> 5;
    const int g = lane >> 2, tig = lane & 3;
    const int i = blockIdx.x;

    const unsigned* svrow = (const unsigned*)g_sv + ((size_t)i << 10) * 32;

    float c[4] = {};
    for (int j0 = 0; j0 < NSEQ; j0 += 128) {
        __syncthreads();
        #pragma unroll
        for (int u = 0; u < 16; u++) {
            int idx = t + 256 * u;
            int j = idx >> 5, dp = idx & 31;
            __nv_bfloat162 b = *(const __nv_bfloat162*)&svrow[(size_t)(j0 + j) * 32 + dp];
            float2 f = __bfloat1622float2(b);
            unsigned* dst = sSv + j * 68 + 2 * dp;
            dst[0] = __float_as_uint(f.x);
            dst[1] = __float_as_uint(f.y);
        }
        #pragma unroll
        for (int u = 0; u < 4; u++) {
            int idx = t + 256 * u;
            int h = idx >> 7, j = idx & 127;
            pHT[h * 132 + j] = f2tf(g_qk[((size_t)h << 20) + ((size_t)i << 10) + j0 + j]);
        }
        __syncthreads();
        #pragma unroll
        for (int k = 0; k < 16; k++) {
            int k0 = k * 8;
            unsigned a0 = pHT[g * 132 + k0 + tig];
            unsigned a2 = pHT[g * 132 + k0 + tig + 4];
            unsigned b0 = sSv[(k0 + tig) * 68 + w * 8 + g];
            unsigned b1 = sSv[(k0 + tig + 4) * 68 + w * 8 + g];
            mma8(c, a0, 0u, a2, 0u, b0, b1);
        }
    }
    {
        int h = g, d = w * 8 + 2 * tig;
        size_t o = (size_t)i * DM + h * DK + d;
        float2 pv = *(const float2*)&g_pv[o];
        *(float2*)&g_attn[o] = make_float2(c[0] + pv.x, c[1] + pv.y);
    }
}

// ---------------------------------------------------------------------------
extern "C" void kernel_launch(void* const* d_in, const int* in_sizes, int n_in,
                              void* d_out, int out_size)
{
    const float* x   = (const float*)d_in[0];
    const float* S   = (const float*)d_in[1];
    const float* Wq  = (const float*)d_in[2];
    const float* bq  = (const float*)d_in[3];
    const float* Wk  = (const float*)d_in[4];
    const float* bk  = (const float*)d_in[5];
    const float* Wv  = (const float*)d_in[6];
    const float* bv  = (const float*)d_in[7];
    const float* Wo  = (const float*)d_in[8];
    const float* bo  = (const float*)d_in[9];
    const float* Wsk = (const float*)d_in[10];
    const float* bsk = (const float*)d_in[11];
    const float* Wsv = (const float*)d_in[12];
    const float* bsv = (const float*)d_in[13];
    float* out = (float*)d_out;

    float *ap;
    cudaGetSymbolAddress((void**)&ap, g_attn);

    cudaFuncSetAttribute(qk_mma, cudaFuncAttributeMaxDynamicSharedMemorySize, QK_SMEM);
    cudaFuncSetAttribute(edge_fused, cudaFuncAttributeMaxDynamicSharedMemorySize, P2_SMEM);

    // Q/K/V projections packed into one launch (384 CTAs -> ~1 wave)
    qkv_proj<<<dim3(DM / 64, NSEQ / 64, 3), 256>>>(x, Wq, bq, Wk, bk, Wv, bv);

    qk_mma<<<dim3(8, 8, 8), 256, QK_SMEM>>>();

    edge_fused<<<dim3(2, NSEQ), 256, P2_SMEM>>>(S, Wsk, bsk, Wsv, bsv);

    softmax_rows<<<NH * NSEQ, 256>>>();

    pv_gemm<<<dim3(16, 8), 256>>>();

    sv_agg<<<NSEQ, 256>>>();

    proj_mma<<<dim3(DM / 64, NSEQ / 64), 256>>>(ap, Wo, bo, out, 0);
}

// round 15
// speedup vs baseline: 1.0053x; 1.0053x over previous
#include <cuda_runtime.h>
#include <cuda_bf16.h>
#include <math.h>
#include <cstdint>

#define NSEQ 1024
#define DM 512
#define NH 8
#define DK 64

// scratch (no cudaMalloc allowed)
__device__ float g_q[NSEQ * DM];
__device__ float g_k[NSEQ * DM];
__device__ float g_v[NSEQ * DM];
__device__ float g_attn[NSEQ * DM];
__device__ float g_pv[NSEQ * DM];
__device__ float g_qk[(size_t)NH * NSEQ * NSEQ];          // 32MB: scores -> probs (in place)
__device__ __nv_bfloat16 g_sv[(size_t)NSEQ * NSEQ * DK];  // 128MB: structure-value proj

__device__ __forceinline__ unsigned f2tf(float f) {
    unsigned u; asm("cvt.rna.tf32.f32 %0, %1;" : "=r"(u) : "f"(f)); return u;
}
__device__ __forceinline__ void mma8(float* c, unsigned a0, unsigned a1, unsigned a2,
                                     unsigned a3, unsigned b0, unsigned b1) {
    asm("mma.sync.aligned.m16n8k8.row.col.f32.tf32.tf32.f32 "
        "{%0,%1,%2,%3},{%4,%5,%6,%7},{%8,%9},{%0,%1,%2,%3};"
        : "+f"(c[0]), "+f"(c[1]), "+f"(c[2]), "+f"(c[3])
        : "r"(a0), "r"(a1), "r"(a2), "r"(a3), "r"(b0), "r"(b1));
}

// ---------------------------------------------------------------------------
// Projection GEMM via 3xTF32 (hh + hl + lh => fp32-grade accuracy).
// Shared device body; qkv_proj packs Q/K/V into one launch via blockIdx.z.
// ---------------------------------------------------------------------------
__device__ __forceinline__ void proj_body(
    const float* __restrict__ A, const float* __restrict__ W,
    const float* __restrict__ bias, float* __restrict__ C, int relu,
    int bm, int bn)
{
    __shared__ unsigned sAhi[64 * 36], sAlo[64 * 36];
    __shared__ unsigned sWhi[32 * 68], sWlo[32 * 68];
    const int t = threadIdx.x, lane = t & 31, w = t >> 5;
    const int g = lane >> 2, tig = lane & 3;
    const int wm = w & 3, wn = w >> 2;

    float c[4][4] = {};

    for (int k0 = 0; k0 < DM; k0 += 32) {
        __syncthreads();
        #pragma unroll
        for (int u = 0; u < 2; u++) {
            int f4 = t + 256 * u;
            {
                int r = f4 >> 3, c4 = (f4 & 7) * 4;
                float4 v = *(const float4*)&A[(size_t)(bm + r) * DM + k0 + c4];
                unsigned* dh = sAhi + r * 36 + c4;
                unsigned* dl = sAlo + r * 36 + c4;
                unsigned h0 = f2tf(v.x), h1 = f2tf(v.y), h2 = f2tf(v.z), h3 = f2tf(v.w);
                dh[0] = h0; dh[1] = h1; dh[2] = h2; dh[3] = h3;
                dl[0] = f2tf(v.x - __uint_as_float(h0));
                dl[1] = f2tf(v.y - __uint_as_float(h1));
                dl[2] = f2tf(v.z - __uint_as_float(h2));
                dl[3] = f2tf(v.w - __uint_as_float(h3));
            }
            {
                int r = f4 >> 4, c4 = (f4 & 15) * 4;
                float4 v = *(const float4*)&W[(size_t)(k0 + r) * DM + bn + c4];
                unsigned* dh = sWhi + r * 68 + c4;
                unsigned* dl = sWlo + r * 68 + c4;
                unsigned h0 = f2tf(v.x), h1 = f2tf(v.y), h2 = f2tf(v.z), h3 = f2tf(v.w);
                dh[0] = h0; dh[1] = h1; dh[2] = h2; dh[3] = h3;
                dl[0] = f2tf(v.x - __uint_as_float(h0));
                dl[1] = f2tf(v.y - __uint_as_float(h1));
                dl[2] = f2tf(v.z - __uint_as_float(h2));
                dl[3] = f2tf(v.w - __uint_as_float(h3));
            }
        }
        __syncthreads();
        #pragma unroll
        for (int ks = 0; ks < 4; ks++) {
            int k8 = ks * 8;
            int r0 = wm * 16;
            unsigned ah0 = sAhi[(r0 + g) * 36 + k8 + tig];
            unsigned ah1 = sAhi[(r0 + g + 8) * 36 + k8 + tig];
            unsigned ah2 = sAhi[(r0 + g) * 36 + k8 + tig + 4];
            unsigned ah3 = sAhi[(r0 + g + 8) * 36 + k8 + tig + 4];
            unsigned al0 = sAlo[(r0 + g) * 36 + k8 + tig];
            unsigned al1 = sAlo[(r0 + g + 8) * 36 + k8 + tig];
            unsigned al2 = sAlo[(r0 + g) * 36 + k8 + tig + 4];
            unsigned al3 = sAlo[(r0 + g + 8) * 36 + k8 + tig + 4];
            #pragma unroll
            for (int nt = 0; nt < 4; nt++) {
                int n = wn * 32 + nt * 8;
                unsigned bh0 = sWhi[(k8 + tig) * 68 + n + g];
                unsigned bh1 = sWhi[(k8 + tig + 4) * 68 + n + g];
                unsigned bl0 = sWlo[(k8 + tig) * 68 + n + g];
                unsigned bl1 = sWlo[(k8 + tig + 4) * 68 + n + g];
                mma8(c[nt], ah0, ah1, ah2, ah3, bh0, bh1);
                mma8(c[nt], ah0, ah1, ah2, ah3, bl0, bl1);
                mma8(c[nt], al0, al1, al2, al3, bh0, bh1);
            }
        }
    }
    #pragma unroll
    for (int nt = 0; nt < 4; nt++) {
        int cc = bn + wn * 32 + nt * 8 + 2 * tig;
        int r  = bm + wm * 16 + g;
        float b0v = bias[cc], b1v = bias[cc + 1];
        float v00 = c[nt][0] + b0v, v01 = c[nt][1] + b1v;
        float v10 = c[nt][2] + b0v, v11 = c[nt][3] + b1v;
        if (relu) {
            v00 = fmaxf(v00, 0.f); v01 = fmaxf(v01, 0.f);
            v10 = fmaxf(v10, 0.f); v11 = fmaxf(v11, 0.f);
        }
        *(float2*)&C[(size_t)r * DM + cc]       = make_float2(v00, v01);
        *(float2*)&C[(size_t)(r + 8) * DM + cc] = make_float2(v10, v11);
    }
}

__global__ void __launch_bounds__(256) proj_mma(
    const float* __restrict__ A, const float* __restrict__ W,
    const float* __restrict__ bias, float* __restrict__ C, int relu)
{
    proj_body(A, W, bias, C, relu, blockIdx.y * 64, blockIdx.x * 64);
}

// One launch for Q, K, V: blockIdx.z selects weights/bias/output/relu.
__global__ void __launch_bounds__(256) qkv_proj(
    const float* __restrict__ x,
    const float* __restrict__ Wq, const float* __restrict__ bq,
    const float* __restrict__ Wk, const float* __restrict__ bk,
    const float* __restrict__ Wv, const float* __restrict__ bv)
{
    const float* W;
    const float* b;
    float* C;
    int relu;
    if (blockIdx.z == 0)      { W = Wq; b = bq; C = g_q; relu = 1; }
    else if (blockIdx.z == 1) { W = Wk; b = bk; C = g_k; relu = 1; }
    else                      { W = Wv; b = bv; C = g_v; relu = 0; }
    proj_body(x, W, b, C, relu, blockIdx.y * 64, blockIdx.x * 64);
}

// ---------------------------------------------------------------------------
// QK precompute: g_qk[h,i,j] = sum_d q[i,h,d]*k[j,h,d]  (raw, unscaled)
// ---------------------------------------------------------------------------
#define QK_SMEM (2 * 128 * 68 * 4)
__global__ void __launch_bounds__(256) qk_mma()
{
    extern __shared__ unsigned sm[];
    unsigned* sQ = sm;
    unsigned* sK = sm + 128 * 68;
    const int t = threadIdx.x, lane = t & 31, w = t >> 5;
    const int g = lane >> 2, tig = lane & 3;
    const int h = blockIdx.z, i0 = blockIdx.y * 128, j0 = blockIdx.x * 128;

    #pragma unroll
    for (int u = 0; u < 8; u++) {
        int f4 = t + 256 * u;
        int row = f4 >> 4;
        int c4 = (f4 & 15) * 4;
        float4 qv = *(const float4*)&g_q[(size_t)(i0 + row) * DM + h * DK + c4];
        unsigned* dq = sQ + row * 68 + c4;
        dq[0] = f2tf(qv.x); dq[1] = f2tf(qv.y); dq[2] = f2tf(qv.z); dq[3] = f2tf(qv.w);
        float4 kv = *(const float4*)&g_k[(size_t)(j0 + row) * DM + h * DK + c4];
        unsigned* dk = sK + row * 68 + c4;
        dk[0] = f2tf(kv.x); dk[1] = f2tf(kv.y); dk[2] = f2tf(kv.z); dk[3] = f2tf(kv.w);
    }
    __syncthreads();

    float c[16][4] = {};
    #pragma unroll
    for (int k0 = 0; k0 < 64; k0 += 8) {
        unsigned a0 = sQ[(16 * w + g) * 68 + k0 + tig];
        unsigned a1 = sQ[(16 * w + g + 8) * 68 + k0 + tig];
        unsigned a2 = sQ[(16 * w + g) * 68 + k0 + tig + 4];
        unsigned a3 = sQ[(16 * w + g + 8) * 68 + k0 + tig + 4];
        #pragma unroll
        for (int nt = 0; nt < 16; nt++) {
            unsigned b0 = sK[(8 * nt + g) * 68 + k0 + tig];
            unsigned b1 = sK[(8 * nt + g) * 68 + k0 + tig + 4];
            mma8(c[nt], a0, a1, a2, a3, b0, b1);
        }
    }
    size_t base = ((size_t)h << 20);
    #pragma unroll
    for (int nt = 0; nt < 16; nt++) {
        int jj = j0 + 8 * nt + 2 * tig;
        int ii = i0 + 16 * w + g;
        *(float2*)&g_qk[base + (size_t)ii * NSEQ + jj] = make_float2(c[nt][0], c[nt][1]);
        *(float2*)&g_qk[base + (size_t)(ii + 8) * NSEQ + jj] = make_float2(c[nt][2], c[nt][3]);
    }
}

// ---------------------------------------------------------------------------
// edge_fused: grid (2 j-halves, 1024 i); each CTA does 4 j-tiles of 128.
// Per tile: [128j x 64e] @ [64e x 128dd] tf32 MMA -> sk (smem, relu) |
// sv (staged in smem -> coalesced STG.128 bf16 to g_sv);
// score MMA: sk @ qT -> g_qk[h,i,j] = (qk + q.sk)*0.125.
// smem words: sW 8704 | sE 8704 (reused as fp32 SV stage) | sSK 8704 | sQT 576 | sB 128
// ---------------------------------------------------------------------------
#define P2_SMEM ((8704 * 3 + 576 + 128) * 4)
__global__ void __launch_bounds__(256, 2) edge_fused(
    const float* __restrict__ S,
    const float* __restrict__ Wsk, const float* __restrict__ bsk,
    const float* __restrict__ Wsv, const float* __restrict__ bsv)
{
    extern __shared__ unsigned sm2[];
    unsigned* sW  = sm2;                 // [64][136]
    unsigned* sE  = sm2 + 8704;          // [128][68] tf32 E; later fp32 SV stage
    unsigned* sSK = sm2 + 17408;         // [128][68] tf32 sk
    unsigned* sQT = sm2 + 26112;         // [64][9]
    float*    sB  = (float*)(sm2 + 26688); // bsk[0:64) | bsv[64:128)
    float*    sSV = (float*)sE;

    const int t = threadIdx.x, lane = t & 31, w = t >> 5;
    const int g = lane >> 2, tig = lane & 3;
    const int i  = blockIdx.y;
    const int jh = blockIdx.x;           // j half: 0 or 1
    const int mq = w & 3, ng = w >> 2;

    const float4* Srow = (const float4*)(S + ((size_t)i * NSEQ + jh * 512) * 64);

    // deep prefetch of tile 0
    float4 pre[8];
    #pragma unroll
    for (int u = 0; u < 8; u++) pre[u] = Srow[t + 256 * u];

    // stage W (Wsk|Wsv) as tf32, pitch 136 (once)
    #pragma unroll
    for (int u = 0; u < 8; u++) {
        int f4 = t + 256 * u;
        int e = f4 >> 5;
        int c4 = (f4 & 31) * 4;
        const float* src = (c4 < 64) ? (Wsk + e * 64 + c4) : (Wsv + e * 64 + c4 - 64);
        float4 v = *(const float4*)src;
        unsigned* dst = sW + e * 136 + c4;
        dst[0] = f2tf(v.x); dst[1] = f2tf(v.y); dst[2] = f2tf(v.z); dst[3] = f2tf(v.w);
    }
    // stage qT [d][h] (once)
    #pragma unroll
    for (int u = 0; u < 2; u++) {
        int idx = t + 256 * u;
        sQT[(idx & 63) * 9 + (idx >> 6)] = f2tf(g_q[(size_t)i * DM + idx]);
    }
    if (t < 128) sB[t] = (t < 64) ? bsk[t] : bsv[t - 64];

    for (int jt = 0; jt < 4; jt++) {
        const int j0 = jh * 512 + jt * 128;
        // STS E tile from prefetch regs (tf32)
        #pragma unroll
        for (int u = 0; u < 8; u++) {
            int f4 = t + 256 * u;
            int j = f4 >> 4;
            int e4 = (f4 & 15) * 4;
            unsigned* dst = sE + j * 68 + e4;
            dst[0] = f2tf(pre[u].x); dst[1] = f2tf(pre[u].y);
            dst[2] = f2tf(pre[u].z); dst[3] = f2tf(pre[u].w);
        }
        __syncthreads();   // sE (and first iter: sW/sQT/sB) ready

        // GEMM1: warp = (mq -> 32 rows, ng -> 64 cols)
        float c[2][8][4] = {};
        #pragma unroll
        for (int k = 0; k < 8; k++) {
            int k0 = k * 8;
            unsigned a[2][4];
            #pragma unroll
            for (int mt = 0; mt < 2; mt++) {
                int r0 = mq * 32 + mt * 16;
                a[mt][0] = sE[(r0 + g) * 68 + k0 + tig];
                a[mt][1] = sE[(r0 + g + 8) * 68 + k0 + tig];
                a[mt][2] = sE[(r0 + g) * 68 + k0 + tig + 4];
                a[mt][3] = sE[(r0 + g + 8) * 68 + k0 + tig + 4];
            }
            #pragma unroll
            for (int nt = 0; nt < 8; nt++) {
                int dd = ng * 64 + nt * 8;
                unsigned b0 = sW[(k0 + tig) * 136 + dd + g];
                unsigned b1 = sW[(k0 + tig + 4) * 136 + dd + g];
                mma8(c[0][nt], a[0][0], a[0][1], a[0][2], a[0][3], b0, b1);
                mma8(c[1][nt], a[1][0], a[1][1], a[1][2], a[1][3], b0, b1);
            }
        }

        // ng==0 warps: sk = relu(c + bsk) -> sSK (tf32)
        if (ng == 0) {
            #pragma unroll
            for (int mt = 0; mt < 2; mt++) {
                int r0 = mq * 32 + mt * 16;
                #pragma unroll
                for (int nt = 0; nt < 8; nt++) {
                    int dd = nt * 8 + 2 * tig;
                    float b0v = sB[dd], b1v = sB[dd + 1];
                    sSK[(r0 + g) * 68 + dd]         = f2tf(fmaxf(c[mt][nt][0] + b0v, 0.f));
                    sSK[(r0 + g) * 68 + dd + 1]     = f2tf(fmaxf(c[mt][nt][1] + b1v, 0.f));
                    sSK[(r0 + g + 8) * 68 + dd]     = f2tf(fmaxf(c[mt][nt][2] + b0v, 0.f));
                    sSK[(r0 + g + 8) * 68 + dd + 1] = f2tf(fmaxf(c[mt][nt][3] + b1v, 0.f));
                }
            }
        }
        __syncthreads();   // sSK complete; sE reads done -> free for SV staging

        if (ng == 1) {
            #pragma unroll
            for (int mt = 0; mt < 2; mt++) {
                int r0 = mq * 32 + mt * 16;
                #pragma unroll
                for (int nt = 0; nt < 8; nt++) {
                    int dv = nt * 8 + 2 * tig;
                    float b0v = sB[64 + dv], b1v = sB[64 + dv + 1];
                    sSV[(r0 + g) * 68 + dv]         = c[mt][nt][0] + b0v;
                    sSV[(r0 + g) * 68 + dv + 1]     = c[mt][nt][1] + b1v;
                    sSV[(r0 + g + 8) * 68 + dv]     = c[mt][nt][2] + b0v;
                    sSV[(r0 + g + 8) * 68 + dv + 1] = c[mt][nt][3] + b1v;
                }
            }
        }

        // prefetch next tile (latency covered by score MMA + epilogue + SV write)
        if (jt < 3) {
            #pragma unroll
            for (int u = 0; u < 8; u++) pre[u] = Srow[(jt + 1) * 2048 + t + 256 * u];
        }

        // score MMA: s2[128j x 8h] = sk @ qT ; warp w = m16 tile
        float cs[4] = {};
        #pragma unroll
        for (int k = 0; k < 8; k++) {
            int k0 = k * 8;
            unsigned a0 = sSK[(16 * w + g) * 68 + k0 + tig];
            unsigned a1 = sSK[(16 * w + g + 8) * 68 + k0 + tig];
            unsigned a2 = sSK[(16 * w + g) * 68 + k0 + tig + 4];
            unsigned a3 = sSK[(16 * w + g + 8) * 68 + k0 + tig + 4];
            unsigned b0 = sQT[(k0 + tig) * 9 + g];
            unsigned b1 = sQT[(k0 + tig + 4) * 9 + g];
            mma8(cs, a0, a1, a2, a3, b0, b1);
        }
        {
            int h0 = 2 * tig;
            int jr = 16 * w + g;
            size_t ibase = ((size_t)i << 10) + j0;
            size_t p00 = ((size_t)h0 << 20) + ibase + jr;
            size_t p01 = ((size_t)(h0 + 1) << 20) + ibase + jr;
            g_qk[p00]     = (g_qk[p00]     + cs[0]) * 0.125f;
            g_qk[p01]     = (g_qk[p01]     + cs[1]) * 0.125f;
            g_qk[p00 + 8] = (g_qk[p00 + 8] + cs[2]) * 0.125f;
            g_qk[p01 + 8] = (g_qk[p01 + 8] + cs[3]) * 0.125f;
        }
        __syncthreads();   // sSV complete

        // cooperative SV write: fp32 smem -> bf16 gmem, coalesced STG.128
        #pragma unroll
        for (int u = 0; u < 4; u++) {
            int idx = t + 256 * u;          // 1024 groups of 8 floats
            int j = idx >> 3;
            int d0 = (idx & 7) * 8;
            const float* src = &sSV[j * 68 + d0];
            __nv_bfloat162 b0 = __float22bfloat162_rn(make_float2(src[0], src[1]));
            __nv_bfloat162 b1 = __float22bfloat162_rn(make_float2(src[2], src[3]));
            __nv_bfloat162 b2 = __float22bfloat162_rn(make_float2(src[4], src[5]));
            __nv_bfloat162 b3 = __float22bfloat162_rn(make_float2(src[6], src[7]));
            uint4 pkt;
            pkt.x = *(unsigned*)&b0; pkt.y = *(unsigned*)&b1;
            pkt.z = *(unsigned*)&b2; pkt.w = *(unsigned*)&b3;
            *(uint4*)((char*)g_sv + (((size_t)i << 10) + j0 + j) * 128 + d0 * 2) = pkt;
        }
        __syncthreads();   // sSV reads done before next iter's STS into sE
    }
}

// ---------------------------------------------------------------------------
// softmax over rows of g_qk (8192 rows of 1024), normalized, in place.
// ---------------------------------------------------------------------------
__global__ void __launch_bounds__(256) softmax_rows()
{
    __shared__ float rbuf[8];
    const int t = threadIdx.x, lane = t & 31, w = t >> 5;
    float4* row4 = (float4*)(g_qk + ((size_t)blockIdx.x << 10));
    float4 v = row4[t];

    float mx = fmaxf(fmaxf(v.x, v.y), fmaxf(v.z, v.w));
    #pragma unroll
    for (int o = 16; o > 0; o >>= 1) mx = fmaxf(mx, __shfl_xor_sync(0xffffffffu, mx, o));
    if (lane == 0) rbuf[w] = mx;
    __syncthreads();
    if (t < 32) {
        float z = (lane < 8) ? rbuf[lane] : -1e30f;
        #pragma unroll
        for (int o = 4; o > 0; o >>= 1) z = fmaxf(z, __shfl_xor_sync(0xffffffffu, z, o));
        if (lane == 0) rbuf[0] = z;
    }
    __syncthreads();
    float m = rbuf[0];
    __syncthreads();

    float4 e;
    e.x = __expf(v.x - m); e.y = __expf(v.y - m);
    e.z = __expf(v.z - m); e.w = __expf(v.w - m);
    float s = e.x + e.y + e.z + e.w;
    #pragma unroll
    for (int o = 16; o > 0; o >>= 1) s += __shfl_xor_sync(0xffffffffu, s, o);
    if (lane == 0) rbuf[w] = s;
    __syncthreads();
    if (t < 32) {
        float z = (lane < 8) ? rbuf[lane] : 0.f;
        #pragma unroll
        for (int o = 4; o > 0; o >>= 1) z += __shfl_xor_sync(0xffffffffu, z, o);
        if (lane == 0) rbuf[0] = z;
    }
    __syncthreads();
    float inv = 1.0f / rbuf[0];
    e.x *= inv; e.y *= inv; e.z *= inv; e.w *= inv;
    row4[t] = e;
}

// ---------------------------------------------------------------------------
// pv_gemm: PV[i, h*64+d] = sum_j p[h,i,j] * v[j, h*64+d]. grid (16 it, 8 h).
// ---------------------------------------------------------------------------
__global__ void __launch_bounds__(256) pv_gemm()
{
    __shared__ unsigned sP[64 * 68];
    __shared__ unsigned sV[64 * 68];
    const int t = threadIdx.x, lane = t & 31, w = t >> 5;
    const int g = lane >> 2, tig = lane & 3;
    const int i0 = blockIdx.x * 64, h = blockIdx.y;
    const int m = w & 3, nh = w >> 2;

    float c[4][4] = {};
    for (int j0 = 0; j0 < NSEQ; j0 += 64) {
        __syncthreads();
        #pragma unroll
        for (int u = 0; u < 4; u++) {
            int f4 = t + 256 * u;
            int r = f4 >> 4;
            int c4 = (f4 & 15) * 4;
            float4 pv = *(const float4*)&g_qk[((size_t)h << 20) + ((size_t)(i0 + r) << 10) + j0 + c4];
            unsigned* dp = sP + r * 68 + c4;
            dp[0] = f2tf(pv.x); dp[1] = f2tf(pv.y); dp[2] = f2tf(pv.z); dp[3] = f2tf(pv.w);
            float4 vv = *(const float4*)&g_v[(size_t)(j0 + r) * DM + h * DK + c4];
            unsigned* dv = sV + r * 68 + c4;
            dv[0] = f2tf(vv.x); dv[1] = f2tf(vv.y); dv[2] = f2tf(vv.z); dv[3] = f2tf(vv.w);
        }
        __syncthreads();
        #pragma unroll
        for (int k = 0; k < 8; k++) {
            int k0 = k * 8;
            unsigned a0 = sP[(m * 16 + g) * 68 + k0 + tig];
            unsigned a1 = sP[(m * 16 + g + 8) * 68 + k0 + tig];
            unsigned a2 = sP[(m * 16 + g) * 68 + k0 + tig + 4];
            unsigned a3 = sP[(m * 16 + g + 8) * 68 + k0 + tig + 4];
            #pragma unroll
            for (int nt = 0; nt < 4; nt++) {
                int d = nh * 32 + nt * 8;
                unsigned b0 = sV[(k0 + tig) * 68 + d + g];
                unsigned b1 = sV[(k0 + tig + 4) * 68 + d + g];
                mma8(c[nt], a0, a1, a2, a3, b0, b1);
            }
        }
    }
    #pragma unroll
    for (int nt = 0; nt < 4; nt++) {
        int d = h * 64 + nh * 32 + nt * 8 + 2 * tig;
        int r = i0 + m * 16 + g;
        *(float2*)&g_pv[(size_t)r * DM + d]       = make_float2(c[nt][0], c[nt][1]);
        *(float2*)&g_pv[(size_t)(r + 8) * DM + d] = make_float2(c[nt][2], c[nt][3]);
    }
}

// ---------------------------------------------------------------------------
// sv_agg (tf32 MMA): attn[i,h*64+d] = PV + sum_j p[h,i,j]*sv[i,j,d].
// ---------------------------------------------------------------------------
__global__ void __launch_bounds__(256) sv_agg()
{
    __shared__ unsigned sSv[128 * 68];
    __shared__ unsigned pHT[8 * 132];
    const int t = threadIdx.x, lane = t & 31, w = t >> 5;
    const int g = lane >> 2, tig = lane & 3;
    const int i = blockIdx.x;

    const unsigned* svrow = (const unsigned*)g_sv + ((size_t)i << 10) * 32;

    float c[4] = {};
    for (int j0 = 0; j0 < NSEQ; j0 += 128) {
        __syncthreads();
        #pragma unroll
        for (int u = 0; u < 16; u++) {
            int idx = t + 256 * u;
            int j = idx >> 5, dp = idx & 31;
            __nv_bfloat162 b = *(const __nv_bfloat162*)&svrow[(size_t)(j0 + j) * 32 + dp];
            float2 f = __bfloat1622float2(b);
            unsigned* dst = sSv + j * 68 + 2 * dp;
            dst[0] = __float_as_uint(f.x);
            dst[1] = __float_as_uint(f.y);
        }
        #pragma unroll
        for (int u = 0; u < 4; u++) {
            int idx = t + 256 * u;
            int h = idx >> 7, j = idx & 127;
            pHT[h * 132 + j] = f2tf(g_qk[((size_t)h << 20) + ((size_t)i << 10) + j0 + j]);
        }
        __syncthreads();
        #pragma unroll
        for (int k = 0; k < 16; k++) {
            int k0 = k * 8;
            unsigned a0 = pHT[g * 132 + k0 + tig];
            unsigned a2 = pHT[g * 132 + k0 + tig + 4];
            unsigned b0 = sSv[(k0 + tig) * 68 + w * 8 + g];
            unsigned b1 = sSv[(k0 + tig + 4) * 68 + w * 8 + g];
            mma8(c, a0, 0u, a2, 0u, b0, b1);
        }
    }
    {
        int h = g, d = w * 8 + 2 * tig;
        size_t o = (size_t)i * DM + h * DK + d;
        float2 pv = *(const float2*)&g_pv[o];
        *(float2*)&g_attn[o] = make_float2(c[0] + pv.x, c[1] + pv.y);
    }
}

// ---------------------------------------------------------------------------
extern "C" void kernel_launch(void* const* d_in, const int* in_sizes, int n_in,
                              void* d_out, int out_size)
{
    const float* x   = (const float*)d_in[0];
    const float* S   = (const float*)d_in[1];
    const float* Wq  = (const float*)d_in[2];
    const float* bq  = (const float*)d_in[3];
    const float* Wk  = (const float*)d_in[4];
    const float* bk  = (const float*)d_in[5];
    const float* Wv  = (const float*)d_in[6];
    const float* bv  = (const float*)d_in[7];
    const float* Wo  = (const float*)d_in[8];
    const float* bo  = (const float*)d_in[9];
    const float* Wsk = (const float*)d_in[10];
    const float* bsk = (const float*)d_in[11];
    const float* Wsv = (const float*)d_in[12];
    const float* bsv = (const float*)d_in[13];
    float* out = (float*)d_out;

    float *ap;
    cudaGetSymbolAddress((void**)&ap, g_attn);

    cudaFuncSetAttribute(qk_mma, cudaFuncAttributeMaxDynamicSharedMemorySize, QK_SMEM);
    cudaFuncSetAttribute(edge_fused, cudaFuncAttributeMaxDynamicSharedMemorySize, P2_SMEM);

    // Q/K/V projections packed into one launch (384 CTAs -> ~1 wave)
    qkv_proj<<<dim3(DM / 64, NSEQ / 64, 3), 256>>>(x, Wq, bq, Wk, bk, Wv, bv);

    qk_mma<<<dim3(8, 8, 8), 256, QK_SMEM>>>();

    edge_fused<<<dim3(2, NSEQ), 256, P2_SMEM>>>(S, Wsk, bsk, Wsv, bsv);

    softmax_rows<<<NH * NSEQ, 256>>>();

    pv_gemm<<<dim3(16, 8), 256>>>();

    sv_agg<<<NSEQ, 256>>>();

    proj_mma<<<dim3(DM / 64, NSEQ / 64), 256>>>(ap, Wo, bo, out, 0);
}

// round 16
// speedup vs baseline: 1.1399x; 1.1340x over previous
#include <cuda_runtime.h>
#include <cuda_bf16.h>
#include <cuda_fp16.h>
#include <math.h>
#include <cstdint>

#define NSEQ 1024
#define DM 512
#define NH 8
#define DK 64

// scratch (no cudaMalloc allowed)
__device__ float g_q[NSEQ * DM];
__device__ float g_k[NSEQ * DM];
__device__ float g_v[NSEQ * DM];
__device__ float g_attn[NSEQ * DM];
__device__ float g_pv[NSEQ * DM];
__device__ float g_qk[(size_t)NH * NSEQ * NSEQ];          // 32MB: scores -> probs (in place)
__device__ __nv_bfloat16 g_sv[(size_t)NSEQ * NSEQ * DK];  // 128MB: structure-value proj

__device__ __forceinline__ unsigned f2tf(float f) {
    unsigned u; asm("cvt.rna.tf32.f32 %0, %1;" : "=r"(u) : "f"(f)); return u;
}
__device__ __forceinline__ unsigned f2h2(float x, float y) {
    __half2 h = __floats2half2_rn(x, y);
    return *(unsigned*)&h;
}
__device__ __forceinline__ void mma8(float* c, unsigned a0, unsigned a1, unsigned a2,
                                     unsigned a3, unsigned b0, unsigned b1) {
    asm("mma.sync.aligned.m16n8k8.row.col.f32.tf32.tf32.f32 "
        "{%0,%1,%2,%3},{%4,%5,%6,%7},{%8,%9},{%0,%1,%2,%3};"
        : "+f"(c[0]), "+f"(c[1]), "+f"(c[2]), "+f"(c[3])
        : "r"(a0), "r"(a1), "r"(a2), "r"(a3), "r"(b0), "r"(b1));
}
// fp16 mma: m16n8k16, f32 accumulate. a regs hold (row, k2t/k2t+1) half pairs.
__device__ __forceinline__ void mma16(float* c, unsigned a0, unsigned a1, unsigned a2,
                                      unsigned a3, unsigned b0, unsigned b1) {
    asm("mma.sync.aligned.m16n8k16.row.col.f32.f16.f16.f32 "
        "{%0,%1,%2,%3},{%4,%5,%6,%7},{%8,%9},{%0,%1,%2,%3};"
        : "+f"(c[0]), "+f"(c[1]), "+f"(c[2]), "+f"(c[3])
        : "r"(a0), "r"(a1), "r"(a2), "r"(a3), "r"(b0), "r"(b1));
}

// ---------------------------------------------------------------------------
// Projection GEMM via 3xTF32 (hh + hl + lh => fp32-grade accuracy).
// ---------------------------------------------------------------------------
__device__ __forceinline__ void proj_body(
    const float* __restrict__ A, const float* __restrict__ W,
    const float* __restrict__ bias, float* __restrict__ C, int relu,
    int bm, int bn)
{
    __shared__ unsigned sAhi[64 * 36], sAlo[64 * 36];
    __shared__ unsigned sWhi[32 * 68], sWlo[32 * 68];
    const int t = threadIdx.x, lane = t & 31, w = t >> 5;
    const int g = lane >> 2, tig = lane & 3;
    const int wm = w & 3, wn = w >> 2;

    float c[4][4] = {};

    for (int k0 = 0; k0 < DM; k0 += 32) {
        __syncthreads();
        #pragma unroll
        for (int u = 0; u < 2; u++) {
            int f4 = t + 256 * u;
            {
                int r = f4 >> 3, c4 = (f4 & 7) * 4;
                float4 v = *(const float4*)&A[(size_t)(bm + r) * DM + k0 + c4];
                unsigned* dh = sAhi + r * 36 + c4;
                unsigned* dl = sAlo + r * 36 + c4;
                unsigned h0 = f2tf(v.x), h1 = f2tf(v.y), h2 = f2tf(v.z), h3 = f2tf(v.w);
                dh[0] = h0; dh[1] = h1; dh[2] = h2; dh[3] = h3;
                dl[0] = f2tf(v.x - __uint_as_float(h0));
                dl[1] = f2tf(v.y - __uint_as_float(h1));
                dl[2] = f2tf(v.z - __uint_as_float(h2));
                dl[3] = f2tf(v.w - __uint_as_float(h3));
            }
            {
                int r = f4 >> 4, c4 = (f4 & 15) * 4;
                float4 v = *(const float4*)&W[(size_t)(k0 + r) * DM + bn + c4];
                unsigned* dh = sWhi + r * 68 + c4;
                unsigned* dl = sWlo + r * 68 + c4;
                unsigned h0 = f2tf(v.x), h1 = f2tf(v.y), h2 = f2tf(v.z), h3 = f2tf(v.w);
                dh[0] = h0; dh[1] = h1; dh[2] = h2; dh[3] = h3;
                dl[0] = f2tf(v.x - __uint_as_float(h0));
                dl[1] = f2tf(v.y - __uint_as_float(h1));
                dl[2] = f2tf(v.z - __uint_as_float(h2));
                dl[3] = f2tf(v.w - __uint_as_float(h3));
            }
        }
        __syncthreads();
        #pragma unroll
        for (int ks = 0; ks < 4; ks++) {
            int k8 = ks * 8;
            int r0 = wm * 16;
            unsigned ah0 = sAhi[(r0 + g) * 36 + k8 + tig];
            unsigned ah1 = sAhi[(r0 + g + 8) * 36 + k8 + tig];
            unsigned ah2 = sAhi[(r0 + g) * 36 + k8 + tig + 4];
            unsigned ah3 = sAhi[(r0 + g + 8) * 36 + k8 + tig + 4];
            unsigned al0 = sAlo[(r0 + g) * 36 + k8 + tig];
            unsigned al1 = sAlo[(r0 + g + 8) * 36 + k8 + tig];
            unsigned al2 = sAlo[(r0 + g) * 36 + k8 + tig + 4];
            unsigned al3 = sAlo[(r0 + g + 8) * 36 + k8 + tig + 4];
            #pragma unroll
            for (int nt = 0; nt < 4; nt++) {
                int n = wn * 32 + nt * 8;
                unsigned bh0 = sWhi[(k8 + tig) * 68 + n + g];
                unsigned bh1 = sWhi[(k8 + tig + 4) * 68 + n + g];
                unsigned bl0 = sWlo[(k8 + tig) * 68 + n + g];
                unsigned bl1 = sWlo[(k8 + tig + 4) * 68 + n + g];
                mma8(c[nt], ah0, ah1, ah2, ah3, bh0, bh1);
                mma8(c[nt], ah0, ah1, ah2, ah3, bl0, bl1);
                mma8(c[nt], al0, al1, al2, al3, bh0, bh1);
            }
        }
    }
    #pragma unroll
    for (int nt = 0; nt < 4; nt++) {
        int cc = bn + wn * 32 + nt * 8 + 2 * tig;
        int r  = bm + wm * 16 + g;
        float b0v = bias[cc], b1v = bias[cc + 1];
        float v00 = c[nt][0] + b0v, v01 = c[nt][1] + b1v;
        float v10 = c[nt][2] + b0v, v11 = c[nt][3] + b1v;
        if (relu) {
            v00 = fmaxf(v00, 0.f); v01 = fmaxf(v01, 0.f);
            v10 = fmaxf(v10, 0.f); v11 = fmaxf(v11, 0.f);
        }
        *(float2*)&C[(size_t)r * DM + cc]       = make_float2(v00, v01);
        *(float2*)&C[(size_t)(r + 8) * DM + cc] = make_float2(v10, v11);
    }
}

__global__ void __launch_bounds__(256) proj_mma(
    const float* __restrict__ A, const float* __restrict__ W,
    const float* __restrict__ bias, float* __restrict__ C, int relu)
{
    proj_body(A, W, bias, C, relu, blockIdx.y * 64, blockIdx.x * 64);
}

__global__ void __launch_bounds__(256) qkv_proj(
    const float* __restrict__ x,
    const float* __restrict__ Wq, const float* __restrict__ bq,
    const float* __restrict__ Wk, const float* __restrict__ bk,
    const float* __restrict__ Wv, const float* __restrict__ bv)
{
    const float* W;
    const float* b;
    float* C;
    int relu;
    if (blockIdx.z == 0)      { W = Wq; b = bq; C = g_q; relu = 1; }
    else if (blockIdx.z == 1) { W = Wk; b = bk; C = g_k; relu = 1; }
    else                      { W = Wv; b = bv; C = g_v; relu = 0; }
    proj_body(x, W, b, C, relu, blockIdx.y * 64, blockIdx.x * 64);
}

// ---------------------------------------------------------------------------
// QK precompute (fp16 mma k16): g_qk[h,i,j] = sum_d q[i,h,d]*k[j,h,d]
// smem: sQ/sK [128 rows][32 half2-words] pitch 36 (conflict-free 4g+tig).
// ---------------------------------------------------------------------------
#define QK_SMEM (2 * 128 * 36 * 4)
__global__ void __launch_bounds__(256) qk_mma()
{
    extern __shared__ unsigned sm[];
    unsigned* sQ = sm;
    unsigned* sK = sm + 128 * 36;
    const int t = threadIdx.x, lane = t & 31, w = t >> 5;
    const int g = lane >> 2, tig = lane & 3;
    const int h = blockIdx.z, i0 = blockIdx.y * 128, j0 = blockIdx.x * 128;

    #pragma unroll
    for (int u = 0; u < 8; u++) {
        int f4 = t + 256 * u;
        int row = f4 >> 4;
        int w2 = (f4 & 15) * 2;       // half2-word index (pairs along d)
        int c4 = (f4 & 15) * 4;
        float4 qv = *(const float4*)&g_q[(size_t)(i0 + row) * DM + h * DK + c4];
        *(uint2*)&sQ[row * 36 + w2] = make_uint2(f2h2(qv.x, qv.y), f2h2(qv.z, qv.w));
        float4 kv = *(const float4*)&g_k[(size_t)(j0 + row) * DM + h * DK + c4];
        *(uint2*)&sK[row * 36 + w2] = make_uint2(f2h2(kv.x, kv.y), f2h2(kv.z, kv.w));
    }
    __syncthreads();

    float c[16][4] = {};
    #pragma unroll
    for (int blk = 0; blk < 4; blk++) {
        int kb = blk * 8;
        unsigned a0 = sQ[(16 * w + g) * 36 + kb + tig];
        unsigned a1 = sQ[(16 * w + g + 8) * 36 + kb + tig];
        unsigned a2 = sQ[(16 * w + g) * 36 + kb + tig + 4];
        unsigned a3 = sQ[(16 * w + g + 8) * 36 + kb + tig + 4];
        #pragma unroll
        for (int nt = 0; nt < 16; nt++) {
            unsigned b0 = sK[(8 * nt + g) * 36 + kb + tig];
            unsigned b1 = sK[(8 * nt + g) * 36 + kb + tig + 4];
            mma16(c[nt], a0, a1, a2, a3, b0, b1);
        }
    }
    size_t base = ((size_t)h << 20);
    #pragma unroll
    for (int nt = 0; nt < 16; nt++) {
        int jj = j0 + 8 * nt + 2 * tig;
        int ii = i0 + 16 * w + g;
        *(float2*)&g_qk[base + (size_t)ii * NSEQ + jj] = make_float2(c[nt][0], c[nt][1]);
        *(float2*)&g_qk[base + (size_t)(ii + 8) * NSEQ + jj] = make_float2(c[nt][2], c[nt][3]);
    }
}

// ---------------------------------------------------------------------------
// edge_fused (fp16 mma k16): one CTA per query row i; 8 j-tiles. Per tile:
//   [128j x 64e] @ [64e x 128dd] fp16 MMA -> sk (fp16 smem, relu) |
//   sv (fp32 smem stage -> coalesced bf16 STG.128)
//   score MMA (fp16): sk @ qT -> g_qk[h,i,j] = (qk + q.sk)*0.125
// smem words: sW 128*36 | sE 128*36 | sSK 128*36 | sSV 128*68 fp32 | sQT 32*9 | sB 128
// ---------------------------------------------------------------------------
#define E_W   0
#define E_E   4608
#define E_SK  9216
#define E_SV  13824
#define E_QT  22528
#define E_B   22816
#define EF_SMEM ((22816 + 128) * 4)

__global__ void __launch_bounds__(256, 2) edge_fused(
    const float* __restrict__ S,
    const float* __restrict__ Wsk, const float* __restrict__ bsk,
    const float* __restrict__ Wsv, const float* __restrict__ bsv)
{
    extern __shared__ unsigned sm2[];
    unsigned* sW  = sm2 + E_W;            // [128 dd][32 epair words] pitch 36
    unsigned* sE  = sm2 + E_E;            // [128 j][32 epair words] pitch 36
    unsigned* sSK = sm2 + E_SK;           // [128 j][32 ddpair words] pitch 36
    float*    sSV = (float*)(sm2 + E_SV); // [128 j][68] fp32
    unsigned* sQT = sm2 + E_QT;           // [32 dpair][8 h] pitch 9
    float*    sB  = (float*)(sm2 + E_B);  // bsk[0:64) | bsv[64:128)

    const int t = threadIdx.x, lane = t & 31, w = t >> 5;
    const int g = lane >> 2, tig = lane & 3;
    const int i = blockIdx.x;
    const int mq = w & 3, ng = w >> 2;

    const float4* Srow = (const float4*)(S + (size_t)i * NSEQ * 64);

    // deep prefetch of tile 0
    float4 pre[8];
    #pragma unroll
    for (int u = 0; u < 8; u++) pre[u] = Srow[t + 256 * u];

    // stage W^T [dd][epair] fp16 (once; L2-hot across CTAs)
    for (int idx = t; idx < 128 * 32; idx += 256) {
        int dd = idx >> 5, ew = idx & 31;
        int e0 = ew * 2;
        float w0, w1;
        if (dd < 64) { w0 = Wsk[e0 * 64 + dd];      w1 = Wsk[(e0 + 1) * 64 + dd]; }
        else         { w0 = Wsv[e0 * 64 + dd - 64]; w1 = Wsv[(e0 + 1) * 64 + dd - 64]; }
        sW[dd * 36 + ew] = f2h2(w0, w1);
    }
    // stage qT [dpair][h] fp16 (once)
    {
        int dp = t & 31, h = t >> 5;
        float2 qv = *(const float2*)&g_q[(size_t)i * DM + h * 64 + 2 * dp];
        sQT[dp * 9 + h] = f2h2(qv.x, qv.y);
    }
    if (t < 128) sB[t] = (t < 64) ? bsk[t] : bsv[t - 64];

    for (int jt = 0; jt < 8; jt++) {
        const int j0 = jt * 128;
        // STS E tile from prefetch regs (fp16 pairs along e, STS.64)
        #pragma unroll
        for (int u = 0; u < 8; u++) {
            int f4 = t + 256 * u;
            int j = f4 >> 4;
            int w2 = (f4 & 15) * 2;
            *(uint2*)&sE[j * 36 + w2] =
                make_uint2(f2h2(pre[u].x, pre[u].y), f2h2(pre[u].z, pre[u].w));
        }
        __syncthreads();   // sync_A: sE ready (first iter: sW/sQT/sB too)

        // GEMM1: warp = (mq -> 32 rows, ng -> 64 cols); 4 k16 blocks
        float c[2][8][4] = {};
        #pragma unroll
        for (int blk = 0; blk < 4; blk++) {
            int kb = blk * 8;
            unsigned a[2][4];
            #pragma unroll
            for (int mt = 0; mt < 2; mt++) {
                int r0 = mq * 32 + mt * 16;
                a[mt][0] = sE[(r0 + g) * 36 + kb + tig];
                a[mt][1] = sE[(r0 + g + 8) * 36 + kb + tig];
                a[mt][2] = sE[(r0 + g) * 36 + kb + tig + 4];
                a[mt][3] = sE[(r0 + g + 8) * 36 + kb + tig + 4];
            }
            #pragma unroll
            for (int nt = 0; nt < 8; nt++) {
                int col = ng * 64 + nt * 8 + g;
                unsigned b0 = sW[col * 36 + kb + tig];
                unsigned b1 = sW[col * 36 + kb + tig + 4];
                mma16(c[0][nt], a[0][0], a[0][1], a[0][2], a[0][3], b0, b1);
                mma16(c[1][nt], a[1][0], a[1][1], a[1][2], a[1][3], b0, b1);
            }
        }

        // ng==0 warps: sk = relu(c + bsk) -> sSK as fp16 pairs (1 STS.32/pair)
        if (ng == 0) {
            #pragma unroll
            for (int mt = 0; mt < 2; mt++) {
                int r0 = mq * 32 + mt * 16;
                #pragma unroll
                for (int nt = 0; nt < 8; nt++) {
                    int dd = nt * 8 + 2 * tig;
                    float b0v = sB[dd], b1v = sB[dd + 1];
                    sSK[(r0 + g) * 36 + nt * 4 + tig] =
                        f2h2(fmaxf(c[mt][nt][0] + b0v, 0.f), fmaxf(c[mt][nt][1] + b1v, 0.f));
                    sSK[(r0 + g + 8) * 36 + nt * 4 + tig] =
                        f2h2(fmaxf(c[mt][nt][2] + b0v, 0.f), fmaxf(c[mt][nt][3] + b1v, 0.f));
                }
            }
        }
        __syncthreads();   // sync_B: sSK complete

        // ng==1 warps: sv = c + bsv -> fp32 stage
        if (ng == 1) {
            #pragma unroll
            for (int mt = 0; mt < 2; mt++) {
                int r0 = mq * 32 + mt * 16;
                #pragma unroll
                for (int nt = 0; nt < 8; nt++) {
                    int dv = nt * 8 + 2 * tig;
                    float b0v = sB[64 + dv], b1v = sB[64 + dv + 1];
                    sSV[(r0 + g) * 68 + dv]         = c[mt][nt][0] + b0v;
                    sSV[(r0 + g) * 68 + dv + 1]     = c[mt][nt][1] + b1v;
                    sSV[(r0 + g + 8) * 68 + dv]     = c[mt][nt][2] + b0v;
                    sSV[(r0 + g + 8) * 68 + dv + 1] = c[mt][nt][3] + b1v;
                }
            }
        }

        // prefetch next tile (latency hidden by score MMA + epilogue + SV write)
        if (jt < 7) {
            #pragma unroll
            for (int u = 0; u < 8; u++) pre[u] = Srow[(jt + 1) * 2048 + t + 256 * u];
        }

        // score MMA (fp16): s2[128j x 8h] = sk @ qT ; warp w = m16 tile
        float cs[4] = {};
        #pragma unroll
        for (int blk = 0; blk < 4; blk++) {
            int kb = blk * 8;
            unsigned a0 = sSK[(16 * w + g) * 36 + kb + tig];
            unsigned a1 = sSK[(16 * w + g + 8) * 36 + kb + tig];
            unsigned a2 = sSK[(16 * w + g) * 36 + kb + tig + 4];
            unsigned a3 = sSK[(16 * w + g + 8) * 36 + kb + tig + 4];
            unsigned b0 = sQT[(kb + tig) * 9 + g];
            unsigned b1 = sQT[(kb + tig + 4) * 9 + g];
            mma16(cs, a0, a1, a2, a3, b0, b1);
        }
        {
            int h0 = 2 * tig;
            int jr = 16 * w + g;
            size_t ibase = ((size_t)i << 10) + j0;
            size_t p00 = ((size_t)h0 << 20) + ibase + jr;
            size_t p01 = ((size_t)(h0 + 1) << 20) + ibase + jr;
            g_qk[p00]     = (g_qk[p00]     + cs[0]) * 0.125f;
            g_qk[p01]     = (g_qk[p01]     + cs[1]) * 0.125f;
            g_qk[p00 + 8] = (g_qk[p00 + 8] + cs[2]) * 0.125f;
            g_qk[p01 + 8] = (g_qk[p01 + 8] + cs[3]) * 0.125f;
        }
        __syncthreads();   // sync_C: sSV complete

        // cooperative SV write: fp32 smem -> bf16 gmem, coalesced STG.128
        #pragma unroll
        for (int u = 0; u < 4; u++) {
            int idx = t + 256 * u;
            int j = idx >> 3;
            int d0 = (idx & 7) * 8;
            const float* src = &sSV[j * 68 + d0];
            __nv_bfloat162 b0 = __float22bfloat162_rn(make_float2(src[0], src[1]));
            __nv_bfloat162 b1 = __float22bfloat162_rn(make_float2(src[2], src[3]));
            __nv_bfloat162 b2 = __float22bfloat162_rn(make_float2(src[4], src[5]));
            __nv_bfloat162 b3 = __float22bfloat162_rn(make_float2(src[6], src[7]));
            uint4 pkt;
            pkt.x = *(unsigned*)&b0; pkt.y = *(unsigned*)&b1;
            pkt.z = *(unsigned*)&b2; pkt.w = *(unsigned*)&b3;
            *(uint4*)((char*)g_sv + (((size_t)i << 10) + j0 + j) * 128 + d0 * 2) = pkt;
        }
        __syncthreads();   // sync_D: sSV reads done before next tile's writes
    }
}

// ---------------------------------------------------------------------------
// softmax over rows of g_qk (8192 rows of 1024), normalized, in place.
// ---------------------------------------------------------------------------
__global__ void __launch_bounds__(256) softmax_rows()
{
    __shared__ float rbuf[8];
    const int t = threadIdx.x, lane = t & 31, w = t >> 5;
    float4* row4 = (float4*)(g_qk + ((size_t)blockIdx.x << 10));
    float4 v = row4[t];

    float mx = fmaxf(fmaxf(v.x, v.y), fmaxf(v.z, v.w));
    #pragma unroll
    for (int o = 16; o > 0; o >>= 1) mx = fmaxf(mx, __shfl_xor_sync(0xffffffffu, mx, o));
    if (lane == 0) rbuf[w] = mx;
    __syncthreads();
    if (t < 32) {
        float z = (lane < 8) ? rbuf[lane] : -1e30f;
        #pragma unroll
        for (int o = 4; o > 0; o >>= 1) z = fmaxf(z, __shfl_xor_sync(0xffffffffu, z, o));
        if (lane == 0) rbuf[0] = z;
    }
    __syncthreads();
    float m = rbuf[0];
    __syncthreads();

    float4 e;
    e.x = __expf(v.x - m); e.y = __expf(v.y - m);
    e.z = __expf(v.z - m); e.w = __expf(v.w - m);
    float s = e.x + e.y + e.z + e.w;
    #pragma unroll
    for (int o = 16; o > 0; o >>= 1) s += __shfl_xor_sync(0xffffffffu, s, o);
    if (lane == 0) rbuf[w] = s;
    __syncthreads();
    if (t < 32) {
        float z = (lane < 8) ? rbuf[lane] : 0.f;
        #pragma unroll
        for (int o = 4; o > 0; o >>= 1) z += __shfl_xor_sync(0xffffffffu, z, o);
        if (lane == 0) rbuf[0] = z;
    }
    __syncthreads();
    float inv = 1.0f / rbuf[0];
    e.x *= inv; e.y *= inv; e.z *= inv; e.w *= inv;
    row4[t] = e;
}

// ---------------------------------------------------------------------------
// pv_gemm: PV[i, h*64+d] = sum_j p[h,i,j] * v[j, h*64+d]. grid (16 it, 8 h).
// ---------------------------------------------------------------------------
__global__ void __launch_bounds__(256) pv_gemm()
{
    __shared__ unsigned sP[64 * 68];
    __shared__ unsigned sV[64 * 68];
    const int t = threadIdx.x, lane = t & 31, w = t >> 5;
    const int g = lane >> 2, tig = lane & 3;
    const int i0 = blockIdx.x * 64, h = blockIdx.y;
    const int m = w & 3, nh = w >> 2;

    float c[4][4] = {};
    for (int j0 = 0; j0 < NSEQ; j0 += 64) {
        __syncthreads();
        #pragma unroll
        for (int u = 0; u < 4; u++) {
            int f4 = t + 256 * u;
            int r = f4 >> 4;
            int c4 = (f4 & 15) * 4;
            float4 pv = *(const float4*)&g_qk[((size_t)h << 20) + ((size_t)(i0 + r) << 10) + j0 + c4];
            unsigned* dp = sP + r * 68 + c4;
            dp[0] = f2tf(pv.x); dp[1] = f2tf(pv.y); dp[2] = f2tf(pv.z); dp[3] = f2tf(pv.w);
            float4 vv = *(const float4*)&g_v[(size_t)(j0 + r) * DM + h * DK + c4];
            unsigned* dv = sV + r * 68 + c4;
            dv[0] = f2tf(vv.x); dv[1] = f2tf(vv.y); dv[2] = f2tf(vv.z); dv[3] = f2tf(vv.w);
        }
        __syncthreads();
        #pragma unroll
        for (int k = 0; k < 8; k++) {
            int k0 = k * 8;
            unsigned a0 = sP[(m * 16 + g) * 68 + k0 + tig];
            unsigned a1 = sP[(m * 16 + g + 8) * 68 + k0 + tig];
            unsigned a2 = sP[(m * 16 + g) * 68 + k0 + tig + 4];
            unsigned a3 = sP[(m * 16 + g + 8) * 68 + k0 + tig + 4];
            #pragma unroll
            for (int nt = 0; nt < 4; nt++) {
                int d = nh * 32 + nt * 8;
                unsigned b0 = sV[(k0 + tig) * 68 + d + g];
                unsigned b1 = sV[(k0 + tig + 4) * 68 + d + g];
                mma8(c[nt], a0, a1, a2, a3, b0, b1);
            }
        }
    }
    #pragma unroll
    for (int nt = 0; nt < 4; nt++) {
        int d = h * 64 + nh * 32 + nt * 8 + 2 * tig;
        int r = i0 + m * 16 + g;
        *(float2*)&g_pv[(size_t)r * DM + d]       = make_float2(c[nt][0], c[nt][1]);
        *(float2*)&g_pv[(size_t)(r + 8) * DM + d] = make_float2(c[nt][2], c[nt][3]);
    }
}

// ---------------------------------------------------------------------------
// sv_agg (tf32 MMA): attn[i,h*64+d] = PV + sum_j p[h,i,j]*sv[i,j,d].
// ---------------------------------------------------------------------------
__global__ void __launch_bounds__(256) sv_agg()
{
    __shared__ unsigned sSv[128 * 68];
    __shared__ unsigned pHT[8 * 132];
    const int t = threadIdx.x, lane = t & 31, w = t >> 5;
    const int g = lane >> 2, tig = lane & 3;
    const int i = blockIdx.x;

    const unsigned* svrow = (const unsigned*)g_sv + ((size_t)i << 10) * 32;

    float c[4] = {};
    for (int j0 = 0; j0 < NSEQ; j0 += 128) {
        __syncthreads();
        #pragma unroll
        for (int u = 0; u < 16; u++) {
            int idx = t + 256 * u;
            int j = idx >> 5, dp = idx & 31;
            __nv_bfloat162 b = *(const __nv_bfloat162*)&svrow[(size_t)(j0 + j) * 32 + dp];
            float2 f = __bfloat1622float2(b);
            unsigned* dst = sSv + j * 68 + 2 * dp;
            dst[0] = __float_as_uint(f.x);
            dst[1] = __float_as_uint(f.y);
        }
        #pragma unroll
        for (int u = 0; u < 4; u++) {
            int idx = t + 256 * u;
            int h = idx >> 7, j = idx & 127;
            pHT[h * 132 + j] = f2tf(g_qk[((size_t)h << 20) + ((size_t)i << 10) + j0 + j]);
        }
        __syncthreads();
        #pragma unroll
        for (int k = 0; k < 16; k++) {
            int k0 = k * 8;
            unsigned a0 = pHT[g * 132 + k0 + tig];
            unsigned a2 = pHT[g * 132 + k0 + tig + 4];
            unsigned b0 = sSv[(k0 + tig) * 68 + w * 8 + g];
            unsigned b1 = sSv[(k0 + tig + 4) * 68 + w * 8 + g];
            mma8(c, a0, 0u, a2, 0u, b0, b1);
        }
    }
    {
        int h = g, d = w * 8 + 2 * tig;
        size_t o = (size_t)i * DM + h * DK + d;
        float2 pv = *(const float2*)&g_pv[o];
        *(float2*)&g_attn[o] = make_float2(c[0] + pv.x, c[1] + pv.y);
    }
}

// ---------------------------------------------------------------------------
extern "C" void kernel_launch(void* const* d_in, const int* in_sizes, int n_in,
                              void* d_out, int out_size)
{
    const float* x   = (const float*)d_in[0];
    const float* S   = (const float*)d_in[1];
    const float* Wq  = (const float*)d_in[2];
    const float* bq  = (const float*)d_in[3];
    const float* Wk  = (const float*)d_in[4];
    const float* bk  = (const float*)d_in[5];
    const float* Wv  = (const float*)d_in[6];
    const float* bv  = (const float*)d_in[7];
    const float* Wo  = (const float*)d_in[8];
    const float* bo  = (const float*)d_in[9];
    const float* Wsk = (const float*)d_in[10];
    const float* bsk = (const float*)d_in[11];
    const float* Wsv = (const float*)d_in[12];
    const float* bsv = (const float*)d_in[13];
    float* out = (float*)d_out;

    float *ap;
    cudaGetSymbolAddress((void**)&ap, g_attn);

    cudaFuncSetAttribute(qk_mma, cudaFuncAttributeMaxDynamicSharedMemorySize, QK_SMEM);
    cudaFuncSetAttribute(edge_fused, cudaFuncAttributeMaxDynamicSharedMemorySize, EF_SMEM);

    // Q/K/V projections packed into one launch (384 CTAs -> ~1 wave)
    qkv_proj<<<dim3(DM / 64, NSEQ / 64, 3), 256>>>(x, Wq, bq, Wk, bk, Wv, bv);

    qk_mma<<<dim3(8, 8, 8), 256, QK_SMEM>>>();

    edge_fused<<<NSEQ, 256, EF_SMEM>>>(S, Wsk, bsk, Wsv, bsv);

    softmax_rows<<<NH * NSEQ, 256>>>();

    pv_gemm<<<dim3(16, 8), 256>>>();

    sv_agg<<<NSEQ, 256>>>();

    proj_mma<<<dim3(DM / 64, NSEQ / 64), 256>>>(ap, Wo, bo, out, 0);
}